// round 1
// baseline (speedup 1.0000x reference)
#include <cuda_runtime.h>
#include <math_constants.h>

#define DIMC   512
#define HEADS  16
#define HD     32
#define BATCH  8
#define SEQ    1024
#define MTOT   (BATCH*SEQ)   // 8192

// ---------------- scratch (no allocations allowed) ----------------
__device__ float g_qkv[(size_t)MTOT * 3 * DIMC];  // [8192][1536]
__device__ float g_y  [(size_t)MTOT * DIMC];      // [8192][512]  (lepe + attn out)

// ============================================================================
// GEMM:  C[M,N] = A[M,K] * B[N,K]^T  (+ optional bias over N)
// 128x128x16 tiles, 256 threads, 8x8 per-thread register tile.
// ============================================================================
__global__ __launch_bounds__(256)
void gemm_nt(const float* __restrict__ A, const float* __restrict__ B,
             float* __restrict__ C, int M, int N, int K,
             const float* __restrict__ bias)
{
    __shared__ float As[128][17];
    __shared__ float Bs[128][17];

    const int tid = threadIdx.x;
    const int tx  = tid & 15;
    const int ty  = tid >> 4;
    const int m0  = blockIdx.y << 7;
    const int n0  = blockIdx.x << 7;

    float acc[8][8];
#pragma unroll
    for (int i = 0; i < 8; i++)
#pragma unroll
        for (int j = 0; j < 8; j++) acc[i][j] = 0.f;

    for (int k0 = 0; k0 < K; k0 += 16) {
#pragma unroll
        for (int l = 0; l < 2; l++) {
            int fi  = tid + (l << 8);           // 0..511
            int row = fi >> 2;                  // 0..127
            int kq  = (fi & 3) << 2;            // 0,4,8,12
            float4 av = *(const float4*)(A + (size_t)(m0 + row) * K + k0 + kq);
            As[row][kq+0] = av.x; As[row][kq+1] = av.y;
            As[row][kq+2] = av.z; As[row][kq+3] = av.w;
            float4 bv = *(const float4*)(B + (size_t)(n0 + row) * K + k0 + kq);
            Bs[row][kq+0] = bv.x; Bs[row][kq+1] = bv.y;
            Bs[row][kq+2] = bv.z; Bs[row][kq+3] = bv.w;
        }
        __syncthreads();

#pragma unroll
        for (int k = 0; k < 16; k++) {
            float af[8], bf[8];
#pragma unroll
            for (int i = 0; i < 8; i++) af[i] = As[ty + (i << 4)][k];
#pragma unroll
            for (int j = 0; j < 8; j++) bf[j] = Bs[tx + (j << 4)][k];
#pragma unroll
            for (int i = 0; i < 8; i++)
#pragma unroll
                for (int j = 0; j < 8; j++) acc[i][j] += af[i] * bf[j];
        }
        __syncthreads();
    }

#pragma unroll
    for (int i = 0; i < 8; i++) {
        int m = m0 + ty + (i << 4);
#pragma unroll
        for (int j = 0; j < 8; j++) {
            int n = n0 + tx + (j << 4);
            float v = acc[i][j];
            if (bias) v += bias[n];
            C[(size_t)m * N + n] = v;
        }
    }
}

// ============================================================================
// LePE depthwise 5x5 conv (zero pad 2).  One block = one pixel, 512 threads =
// channels.  Writes y[pix][c] = bias + conv.  (attention adds into y after)
// ============================================================================
__global__ __launch_bounds__(512)
void lepe_conv(const float* __restrict__ x, const float* __restrict__ w,
               const float* __restrict__ bias, float* __restrict__ y)
{
    const int c   = threadIdx.x;           // 0..511
    const int pix = blockIdx.x;            // 0..8191
    const int j   = pix & 31;
    const int i   = (pix >> 5) & 31;
    const int b   = pix >> 10;

    float wr[25];
#pragma unroll
    for (int t = 0; t < 25; t++) wr[t] = w[c * 25 + t];

    float acc = bias[c];
#pragma unroll
    for (int u = 0; u < 5; u++) {
        int ii = i + u - 2;
        if (ii < 0 || ii >= 32) continue;
#pragma unroll
        for (int v = 0; v < 5; v++) {
            int jj = j + v - 2;
            if (jj < 0 || jj >= 32) continue;
            acc += x[((size_t)((b * 32 + ii) * 32 + jj)) * DIMC + c] * wr[u * 5 + v];
        }
    }
    y[(size_t)pix * DIMC + c] = acc;
}

// ============================================================================
// Attention: flash-style, fp32.  CTA = (q-block of 64 rows, head, batch).
// 256 threads = 16x16.  K-tiles of 64.  Online softmax, P staged in smem,
// V stored transposed.  Adds result into g_y (which already holds lepe).
// ============================================================================
#define QB 64
#define KB 64

__global__ __launch_bounds__(256)
void attn_kernel(const float* __restrict__ qkv, float* __restrict__ y)
{
    __shared__ float Qs[QB][34];     // q rows (scaled)
    __shared__ float Ks[KB][34];     // k rows
    __shared__ float Vt[HD][66];     // V transposed: [d][kcol]
    __shared__ float Ps[QB][66];     // probabilities

    const int tid = threadIdx.x;
    const int tx  = tid & 15;
    const int ty  = tid >> 4;
    const int qb0 = blockIdx.x * QB;        // q row block within seq
    const int h   = blockIdx.y;
    const int b   = blockIdx.z;
    const float scale = 0.17677669529663687f;   // 32^-0.5

    const size_t rowstride = 3 * DIMC;          // 1536
    const size_t base   = (size_t)b * SEQ * rowstride + h * HD;
    const size_t kbase  = base + DIMC;          // K section
    const size_t vbase  = base + 2 * DIMC;      // V section

    // ---- load Q block (64 x 32), fold in scale ----
#pragma unroll
    for (int l = 0; l < 2; l++) {
        int fi = tid + (l << 8);        // 0..511
        int r  = fi >> 3;               // 0..63
        int dq = (fi & 7) << 2;         // 0,4,..,28
        float4 v = *(const float4*)(qkv + base + (size_t)(qb0 + r) * rowstride + dq);
        Qs[r][dq+0] = v.x * scale; Qs[r][dq+1] = v.y * scale;
        Qs[r][dq+2] = v.z * scale; Qs[r][dq+3] = v.w * scale;
    }

    float o[4][2];
    float mrow[4], lrow[4];
#pragma unroll
    for (int i = 0; i < 4; i++) {
        o[i][0] = 0.f; o[i][1] = 0.f;
        mrow[i] = -CUDART_INF_F; lrow[i] = 0.f;
    }

    for (int kt = 0; kt < SEQ / KB; kt++) {
        __syncthreads();   // prior PV done (also covers Qs load on iter 0)
        // ---- load K tile and V tile (transposed) ----
#pragma unroll
        for (int l = 0; l < 2; l++) {
            int fi = tid + (l << 8);
            int r  = fi >> 3;
            int dq = (fi & 7) << 2;
            float4 kv = *(const float4*)(qkv + kbase + (size_t)(kt * KB + r) * rowstride + dq);
            Ks[r][dq+0] = kv.x; Ks[r][dq+1] = kv.y;
            Ks[r][dq+2] = kv.z; Ks[r][dq+3] = kv.w;
            float4 vv = *(const float4*)(qkv + vbase + (size_t)(kt * KB + r) * rowstride + dq);
            Vt[dq+0][r] = vv.x; Vt[dq+1][r] = vv.y;
            Vt[dq+2][r] = vv.z; Vt[dq+3][r] = vv.w;
        }
        __syncthreads();

        // ---- S = Q K^T (4x4 fragment per thread) ----
        float s[4][4];
#pragma unroll
        for (int i = 0; i < 4; i++)
#pragma unroll
            for (int j = 0; j < 4; j++) s[i][j] = 0.f;

#pragma unroll
        for (int kd = 0; kd < HD; kd += 2) {
            float2 qf[4], kf[4];
#pragma unroll
            for (int i = 0; i < 4; i++) qf[i] = *(const float2*)&Qs[(i << 4) + ty][kd];
#pragma unroll
            for (int j = 0; j < 4; j++) kf[j] = *(const float2*)&Ks[(j << 4) + tx][kd];
#pragma unroll
            for (int i = 0; i < 4; i++)
#pragma unroll
                for (int j = 0; j < 4; j++)
                    s[i][j] += qf[i].x * kf[j].x + qf[i].y * kf[j].y;
        }

        // ---- online softmax (rows reduced over 16 tx lanes) ----
#pragma unroll
        for (int i = 0; i < 4; i++) {
            float tm = s[i][0];
#pragma unroll
            for (int j = 1; j < 4; j++) tm = fmaxf(tm, s[i][j]);
#pragma unroll
            for (int off = 8; off >= 1; off >>= 1)
                tm = fmaxf(tm, __shfl_xor_sync(0xffffffffu, tm, off));

            float mn   = fmaxf(mrow[i], tm);
            float corr = __expf(mrow[i] - mn);
            mrow[i] = mn;

            float psum = 0.f;
            float p[4];
#pragma unroll
            for (int j = 0; j < 4; j++) { p[j] = __expf(s[i][j] - mn); psum += p[j]; }
#pragma unroll
            for (int off = 8; off >= 1; off >>= 1)
                psum += __shfl_xor_sync(0xffffffffu, psum, off);

            lrow[i] = lrow[i] * corr + psum;
            o[i][0] *= corr; o[i][1] *= corr;
#pragma unroll
            for (int j = 0; j < 4; j++) Ps[(i << 4) + ty][(j << 4) + tx] = p[j];
        }
        __syncthreads();

        // ---- O += P * V ----
#pragma unroll
        for (int jj = 0; jj < KB; jj += 2) {
            float2 pf[4], vf[2];
#pragma unroll
            for (int i = 0; i < 4; i++) pf[i] = *(const float2*)&Ps[(i << 4) + ty][jj];
#pragma unroll
            for (int d = 0; d < 2; d++) vf[d] = *(const float2*)&Vt[(d << 4) + tx][jj];
#pragma unroll
            for (int i = 0; i < 4; i++)
#pragma unroll
                for (int d = 0; d < 2; d++)
                    o[i][d] += pf[i].x * vf[d].x + pf[i].y * vf[d].y;
        }
    }

    // ---- finalize: y += O / l ----
#pragma unroll
    for (int i = 0; i < 4; i++) {
        float inv = 1.f / lrow[i];
        int n = qb0 + (i << 4) + ty;
        size_t yb = ((size_t)b * SEQ + n) * DIMC + h * HD + tx;
        y[yb]      += o[i][0] * inv;
        y[yb + 16] += o[i][1] * inv;
    }
}

// ============================================================================
// launch
// ============================================================================
extern "C" void kernel_launch(void* const* d_in, const int* in_sizes, int n_in,
                              void* d_out, int out_size)
{
    const float* x      = (const float*)d_in[0];
    const float* w_qkv  = (const float*)d_in[1];
    const float* w_proj = (const float*)d_in[2];
    const float* b_proj = (const float*)d_in[3];
    const float* w_lepe = (const float*)d_in[4];
    const float* b_lepe = (const float*)d_in[5];
    float* out = (float*)d_out;

    void* p_qkv = nullptr;
    void* p_y   = nullptr;
    cudaGetSymbolAddress(&p_qkv, g_qkv);
    cudaGetSymbolAddress(&p_y,   g_y);
    float* qkv = (float*)p_qkv;
    float* y   = (float*)p_y;

    // 1) QKV GEMM: [8192,1536] = x[8192,512] @ w_qkv[1536,512]^T
    gemm_nt<<<dim3(3 * DIMC / 128, MTOT / 128), 256>>>(x, w_qkv, qkv,
                                                       MTOT, 3 * DIMC, DIMC, nullptr);
    // 2) LePE conv -> y
    lepe_conv<<<MTOT, DIMC>>>(x, w_lepe, b_lepe, y);
    // 3) attention, y += attn_out
    attn_kernel<<<dim3(SEQ / QB, HEADS, BATCH), 256>>>(qkv, y);
    // 4) proj: out = y @ w_proj^T + b_proj
    gemm_nt<<<dim3(DIMC / 128, MTOT / 128), 256>>>(y, w_proj, out,
                                                   MTOT, DIMC, DIMC, b_proj);
}

// round 4
// speedup vs baseline: 1.4798x; 1.4798x over previous
#include <cuda_runtime.h>
#include <math_constants.h>

#define DIMC   512
#define HEADS  16
#define HD     32
#define BATCH  8
#define SEQ    1024
#define MTOT   (BATCH*SEQ)   // 8192

// ---------------- scratch (no allocations allowed) ----------------
__device__ float g_qkv[(size_t)MTOT * 3 * DIMC];  // [8192][1536]
__device__ float g_y  [(size_t)MTOT * DIMC];      // [8192][512]  (lepe + attn out)

// ---------------- helpers ----------------
__device__ __forceinline__ unsigned f2tf(float x) {
    unsigned r; asm("cvt.rna.tf32.f32 %0, %1;" : "=r"(r) : "f"(x)); return r;
}
__device__ __forceinline__ uint2 split2(float x) {
    unsigned hi = f2tf(x);
    unsigned lo = f2tf(x - __uint_as_float(hi));
    return make_uint2(hi, lo);
}
__device__ __forceinline__ void mma8(float* c,
                                     unsigned a0, unsigned a1, unsigned a2, unsigned a3,
                                     unsigned b0, unsigned b1) {
    asm volatile("mma.sync.aligned.m16n8k8.row.col.f32.tf32.tf32.f32 "
                 "{%0,%1,%2,%3},{%4,%5,%6,%7},{%8,%9},{%0,%1,%2,%3};"
                 : "+f"(c[0]), "+f"(c[1]), "+f"(c[2]), "+f"(c[3])
                 : "r"(a0), "r"(a1), "r"(a2), "r"(a3), "r"(b0), "r"(b1));
}

// ============================================================================
// GEMM (3xTF32):  C[M,N] = A[M,K] * B[N,K]^T  (+ optional bias over N)
// 128x128 CTA tile, KTILE=16, 8 warps of 64x32, m16n8k8 tf32 mma.
// ============================================================================
#define KT 16

__global__ __launch_bounds__(256)
void gemm_tc(const float* __restrict__ A, const float* __restrict__ B,
             float* __restrict__ C, int M, int N, int K,
             const float* __restrict__ bias)
{
    __shared__ __align__(16) uint2 As[128][19];   // {hi,lo} tf32 pairs, pad 19
    __shared__ __align__(16) uint2 Bs[128][19];

    const int tid   = threadIdx.x;
    const int wid   = tid >> 5;
    const int lane  = tid & 31;
    const int g     = lane >> 2;          // 0..7
    const int i     = lane & 3;           // 0..3
    const int warpM = wid & 1;            // 2
    const int warpN = wid >> 1;           // 4
    const int mbase = warpM * 64;
    const int nbase = warpN * 32;
    const int m0    = blockIdx.y << 7;
    const int n0    = blockIdx.x << 7;

    // loader mapping: each thread loads 8 A floats + 8 B floats per stage
    const int lrow  = tid >> 1;           // 0..127
    const int lcol  = (tid & 1) << 3;     // 0 or 8
    const float* aptr = A + (size_t)(m0 + lrow) * K + lcol;
    const float* bptr = B + (size_t)(n0 + lrow) * K + lcol;

    float c[4][4][4];
#pragma unroll
    for (int mf = 0; mf < 4; mf++)
#pragma unroll
        for (int nf = 0; nf < 4; nf++)
#pragma unroll
            for (int t = 0; t < 4; t++) c[mf][nf][t] = 0.f;

    const int nstages = K / KT;  // 32

    float4 ra0 = *(const float4*)(aptr);
    float4 ra1 = *(const float4*)(aptr + 4);
    float4 rb0 = *(const float4*)(bptr);
    float4 rb1 = *(const float4*)(bptr + 4);

    for (int s = 0; s < nstages; s++) {
        // store stage s
        As[lrow][lcol+0] = split2(ra0.x); As[lrow][lcol+1] = split2(ra0.y);
        As[lrow][lcol+2] = split2(ra0.z); As[lrow][lcol+3] = split2(ra0.w);
        As[lrow][lcol+4] = split2(ra1.x); As[lrow][lcol+5] = split2(ra1.y);
        As[lrow][lcol+6] = split2(ra1.z); As[lrow][lcol+7] = split2(ra1.w);
        Bs[lrow][lcol+0] = split2(rb0.x); Bs[lrow][lcol+1] = split2(rb0.y);
        Bs[lrow][lcol+2] = split2(rb0.z); Bs[lrow][lcol+3] = split2(rb0.w);
        Bs[lrow][lcol+4] = split2(rb1.x); Bs[lrow][lcol+5] = split2(rb1.y);
        Bs[lrow][lcol+6] = split2(rb1.z); Bs[lrow][lcol+7] = split2(rb1.w);
        __syncthreads();

        // prefetch stage s+1
        if (s + 1 < nstages) {
            int ko = (s + 1) * KT;
            ra0 = *(const float4*)(aptr + ko);
            ra1 = *(const float4*)(aptr + ko + 4);
            rb0 = *(const float4*)(bptr + ko);
            rb1 = *(const float4*)(bptr + ko + 4);
        }

        // compute 2 ksteps of 8
#pragma unroll
        for (int ks = 0; ks < 2; ks++) {
            const int k0i = (ks << 3) + i;
            uint2 a[4][4];
            uint2 b[4][2];
#pragma unroll
            for (int mf = 0; mf < 4; mf++) {
                int r = mbase + (mf << 4);
                a[mf][0] = As[r + g    ][k0i];
                a[mf][1] = As[r + g + 8][k0i];
                a[mf][2] = As[r + g    ][k0i + 4];
                a[mf][3] = As[r + g + 8][k0i + 4];
            }
#pragma unroll
            for (int nf = 0; nf < 4; nf++) {
                int r = nbase + (nf << 3) + g;
                b[nf][0] = Bs[r][k0i];
                b[nf][1] = Bs[r][k0i + 4];
            }
#pragma unroll
            for (int mf = 0; mf < 4; mf++)
#pragma unroll
                for (int nf = 0; nf < 4; nf++) {
                    mma8(c[mf][nf], a[mf][0].x, a[mf][1].x, a[mf][2].x, a[mf][3].x,
                                    b[nf][0].x, b[nf][1].x);           // hi*hi
                    mma8(c[mf][nf], a[mf][0].x, a[mf][1].x, a[mf][2].x, a[mf][3].x,
                                    b[nf][0].y, b[nf][1].y);           // hi*lo
                    mma8(c[mf][nf], a[mf][0].y, a[mf][1].y, a[mf][2].y, a[mf][3].y,
                                    b[nf][0].x, b[nf][1].x);           // lo*hi
                }
        }
        __syncthreads();
    }

    // epilogue
#pragma unroll
    for (int mf = 0; mf < 4; mf++) {
        int r0 = m0 + mbase + (mf << 4) + g;
        int r1 = r0 + 8;
#pragma unroll
        for (int nf = 0; nf < 4; nf++) {
            int col = n0 + nbase + (nf << 3) + (i << 1);
            float bx = bias ? bias[col]     : 0.f;
            float by = bias ? bias[col + 1] : 0.f;
            float2 v0 = make_float2(c[mf][nf][0] + bx, c[mf][nf][1] + by);
            float2 v1 = make_float2(c[mf][nf][2] + bx, c[mf][nf][3] + by);
            *(float2*)&C[(size_t)r0 * N + col] = v0;
            *(float2*)&C[(size_t)r1 * N + col] = v1;
        }
    }
}

// ============================================================================
// LePE depthwise 5x5 conv (zero pad 2).  One block = one pixel.
// ============================================================================
__global__ __launch_bounds__(512)
void lepe_conv(const float* __restrict__ x, const float* __restrict__ w,
               const float* __restrict__ bias, float* __restrict__ y)
{
    const int c   = threadIdx.x;
    const int pix = blockIdx.x;
    const int j   = pix & 31;
    const int i   = (pix >> 5) & 31;
    const int b   = pix >> 10;

    float wr[25];
#pragma unroll
    for (int t = 0; t < 25; t++) wr[t] = w[c * 25 + t];

    float acc = bias[c];
#pragma unroll
    for (int u = 0; u < 5; u++) {
        int ii = i + u - 2;
        if (ii < 0 || ii >= 32) continue;
#pragma unroll
        for (int v = 0; v < 5; v++) {
            int jj = j + v - 2;
            if (jj < 0 || jj >= 32) continue;
            acc += x[((size_t)((b * 32 + ii) * 32 + jj)) * DIMC + c] * wr[u * 5 + v];
        }
    }
    y[(size_t)pix * DIMC + c] = acc;
}

// ============================================================================
// Attention (tf32 tensor-core flash).  CTA = (64 q-rows, head, batch).
// 4 warps, each owns 16 q-rows (one m16 fragment row).  KB=64 K-tiles.
// ============================================================================
#define QB 64
#define KB 64

__global__ __launch_bounds__(128)
void attn_tc(const float* __restrict__ qkv, float* __restrict__ y)
{
    __shared__ __align__(16) unsigned Qs[QB][36];   // tf32 bits, stride 36
    __shared__ __align__(16) unsigned Ks[KB][36];
    __shared__ __align__(16) unsigned Vs[KB][36];   // [seq][d]
    __shared__ __align__(16) unsigned Ps[QB][68];   // tf32 P, stride 68

    const int tid  = threadIdx.x;
    const int warp = tid >> 5;
    const int lane = tid & 31;
    const int g    = lane >> 2;
    const int i    = lane & 3;
    const int w16  = warp << 4;

    const int qb0 = blockIdx.x * QB;
    const int h   = blockIdx.y;
    const int b   = blockIdx.z;
    const float scale = 0.17677669529663687f;  // 32^-0.5

    const size_t rowstride = 3 * DIMC;
    const size_t base  = (size_t)b * SEQ * rowstride + h * HD;
    const size_t kbase = base + DIMC;
    const size_t vbase = base + 2 * DIMC;

    // ---- load Q (64x32), scale, convert to tf32 ----
#pragma unroll
    for (int l = 0; l < 4; l++) {
        int fi = tid + (l << 7);          // 0..511 float4 slots
        int r  = fi >> 3;
        int d4 = (fi & 7) << 2;
        float4 v = *(const float4*)(qkv + base + (size_t)(qb0 + r) * rowstride + d4);
        uint4 t;
        t.x = f2tf(v.x * scale); t.y = f2tf(v.y * scale);
        t.z = f2tf(v.z * scale); t.w = f2tf(v.w * scale);
        *(uint4*)&Qs[r][d4] = t;
    }
    __syncthreads();

    // Q fragments (row block = this warp's 16 rows), 4 ksteps over d=32
    unsigned qa[4][4];
#pragma unroll
    for (int ks = 0; ks < 4; ks++) {
        int kc = (ks << 3) + i;
        qa[ks][0] = Qs[w16 + g    ][kc];
        qa[ks][1] = Qs[w16 + g + 8][kc];
        qa[ks][2] = Qs[w16 + g    ][kc + 4];
        qa[ks][3] = Qs[w16 + g + 8][kc + 4];
    }

    float o[4][4];
#pragma unroll
    for (int nf = 0; nf < 4; nf++)
#pragma unroll
        for (int t = 0; t < 4; t++) o[nf][t] = 0.f;
    float m0r = -CUDART_INF_F, m1r = -CUDART_INF_F;
    float l0r = 0.f, l1r = 0.f;

    for (int kt = 0; kt < SEQ / KB; kt++) {
        __syncthreads();   // previous tile fully consumed
        // ---- load K,V tiles (64x32 each), convert to tf32 ----
#pragma unroll
        for (int l = 0; l < 4; l++) {
            int fi = tid + (l << 7);
            int r  = fi >> 3;
            int d4 = (fi & 7) << 2;
            size_t roff = (size_t)(kt * KB + r) * rowstride + d4;
            float4 kv = *(const float4*)(qkv + kbase + roff);
            uint4 tk;
            tk.x = f2tf(kv.x); tk.y = f2tf(kv.y); tk.z = f2tf(kv.z); tk.w = f2tf(kv.w);
            *(uint4*)&Ks[r][d4] = tk;
            float4 vv = *(const float4*)(qkv + vbase + roff);
            uint4 tv;
            tv.x = f2tf(vv.x); tv.y = f2tf(vv.y); tv.z = f2tf(vv.z); tv.w = f2tf(vv.w);
            *(uint4*)&Vs[r][d4] = tv;
        }
        __syncthreads();

        // ---- S = Q K^T : 8 n-frags of 8 cols ----
        float s[8][4];
#pragma unroll
        for (int nf = 0; nf < 8; nf++) {
            s[nf][0] = 0.f; s[nf][1] = 0.f; s[nf][2] = 0.f; s[nf][3] = 0.f;
        }
#pragma unroll
        for (int nf = 0; nf < 8; nf++) {
            int nr = (nf << 3) + g;
#pragma unroll
            for (int ks = 0; ks < 4; ks++) {
                int kc = (ks << 3) + i;
                unsigned b0 = Ks[nr][kc];
                unsigned b1 = Ks[nr][kc + 4];
                mma8(s[nf], qa[ks][0], qa[ks][1], qa[ks][2], qa[ks][3], b0, b1);
            }
        }

        // ---- online softmax (rows g and g+8) ----
        float mx0 = -CUDART_INF_F, mx1 = -CUDART_INF_F;
#pragma unroll
        for (int nf = 0; nf < 8; nf++) {
            mx0 = fmaxf(mx0, fmaxf(s[nf][0], s[nf][1]));
            mx1 = fmaxf(mx1, fmaxf(s[nf][2], s[nf][3]));
        }
        mx0 = fmaxf(mx0, __shfl_xor_sync(0xffffffffu, mx0, 1));
        mx0 = fmaxf(mx0, __shfl_xor_sync(0xffffffffu, mx0, 2));
        mx1 = fmaxf(mx1, __shfl_xor_sync(0xffffffffu, mx1, 1));
        mx1 = fmaxf(mx1, __shfl_xor_sync(0xffffffffu, mx1, 2));

        float mn0 = fmaxf(m0r, mx0);
        float mn1 = fmaxf(m1r, mx1);
        float cor0 = __expf(m0r - mn0);
        float cor1 = __expf(m1r - mn1);
        m0r = mn0; m1r = mn1;

        float ps0 = 0.f, ps1 = 0.f;
#pragma unroll
        for (int nf = 0; nf < 8; nf++) {
            float p0 = __expf(s[nf][0] - mn0);
            float p1 = __expf(s[nf][1] - mn0);
            float p2 = __expf(s[nf][2] - mn1);
            float p3 = __expf(s[nf][3] - mn1);
            ps0 += p0 + p1;
            ps1 += p2 + p3;
            int col = (nf << 3) + (i << 1);
            *(uint2*)&Ps[w16 + g    ][col] = make_uint2(f2tf(p0), f2tf(p1));
            *(uint2*)&Ps[w16 + g + 8][col] = make_uint2(f2tf(p2), f2tf(p3));
        }
        ps0 += __shfl_xor_sync(0xffffffffu, ps0, 1);
        ps0 += __shfl_xor_sync(0xffffffffu, ps0, 2);
        ps1 += __shfl_xor_sync(0xffffffffu, ps1, 1);
        ps1 += __shfl_xor_sync(0xffffffffu, ps1, 2);
        l0r = l0r * cor0 + ps0;
        l1r = l1r * cor1 + ps1;

#pragma unroll
        for (int nf = 0; nf < 4; nf++) {
            o[nf][0] *= cor0; o[nf][1] *= cor0;
            o[nf][2] *= cor1; o[nf][3] *= cor1;
        }
        __syncwarp();   // P smem visible within warp (own rows only)

        // ---- O += P * V : k=64 (8 ksteps), n=32 (4 nfrags) ----
#pragma unroll
        for (int ks = 0; ks < 8; ks++) {
            int kc = (ks << 3) + i;
            unsigned pa0 = Ps[w16 + g    ][kc];
            unsigned pa1 = Ps[w16 + g + 8][kc];
            unsigned pa2 = Ps[w16 + g    ][kc + 4];
            unsigned pa3 = Ps[w16 + g + 8][kc + 4];
            int kr0 = (ks << 3) + i;
#pragma unroll
            for (int nf = 0; nf < 4; nf++) {
                int nc = (nf << 3) + g;
                unsigned vb0 = Vs[kr0    ][nc];
                unsigned vb1 = Vs[kr0 + 4][nc];
                mma8(o[nf], pa0, pa1, pa2, pa3, vb0, vb1);
            }
        }
    }

    // ---- finalize: y += O / l ----
    float inv0 = 1.f / l0r;
    float inv1 = 1.f / l1r;
    int r0 = b * SEQ + qb0 + w16 + g;
    int r1 = r0 + 8;
#pragma unroll
    for (int nf = 0; nf < 4; nf++) {
        int col = h * HD + (nf << 3) + (i << 1);
        size_t i00 = (size_t)r0 * DIMC + col;
        size_t i10 = (size_t)r1 * DIMC + col;
        y[i00]     += o[nf][0] * inv0;
        y[i00 + 1] += o[nf][1] * inv0;
        y[i10]     += o[nf][2] * inv1;
        y[i10 + 1] += o[nf][3] * inv1;
    }
}

// ============================================================================
// launch
// ============================================================================
extern "C" void kernel_launch(void* const* d_in, const int* in_sizes, int n_in,
                              void* d_out, int out_size)
{
    const float* x      = (const float*)d_in[0];
    const float* w_qkv  = (const float*)d_in[1];
    const float* w_proj = (const float*)d_in[2];
    const float* b_proj = (const float*)d_in[3];
    const float* w_lepe = (const float*)d_in[4];
    const float* b_lepe = (const float*)d_in[5];
    float* out = (float*)d_out;

    void* p_qkv = nullptr;
    void* p_y   = nullptr;
    cudaGetSymbolAddress(&p_qkv, g_qkv);
    cudaGetSymbolAddress(&p_y,   g_y);
    float* qkv = (float*)p_qkv;
    float* y   = (float*)p_y;

    // 1) QKV GEMM: [8192,1536] = x[8192,512] @ w_qkv[1536,512]^T
    gemm_tc<<<dim3(3 * DIMC / 128, MTOT / 128), 256>>>(x, w_qkv, qkv,
                                                       MTOT, 3 * DIMC, DIMC, nullptr);
    // 2) LePE conv -> y
    lepe_conv<<<MTOT, DIMC>>>(x, w_lepe, b_lepe, y);
    // 3) attention, y += attn_out
    attn_tc<<<dim3(SEQ / QB, HEADS, BATCH), 128>>>(qkv, y);
    // 4) proj: out = y @ w_proj^T + b_proj
    gemm_tc<<<dim3(DIMC / 128, MTOT / 128), 256>>>(y, w_proj, out,
                                                   MTOT, DIMC, DIMC, b_proj);
}

// round 5
// speedup vs baseline: 2.7835x; 1.8810x over previous
#include <cuda_runtime.h>
#include <math_constants.h>

#define DIMC   512
#define HEADS  16
#define HD     32
#define BATCH  8
#define SEQ    1024
#define MTOT   (BATCH*SEQ)   // 8192

// ---------------- scratch (no allocations allowed) ----------------
__device__ float g_qkv[(size_t)MTOT * 3 * DIMC];  // [8192][1536]
__device__ float g_y  [(size_t)MTOT * DIMC];      // [8192][512]  (lepe + attn out)

// ---------------- helpers ----------------
__device__ __forceinline__ unsigned f2tf(float x) {
    unsigned r; asm("cvt.rna.tf32.f32 %0, %1;" : "=r"(r) : "f"(x)); return r;
}
__device__ __forceinline__ void mma8(float* c,
                                     unsigned a0, unsigned a1, unsigned a2, unsigned a3,
                                     unsigned b0, unsigned b1) {
    asm volatile("mma.sync.aligned.m16n8k8.row.col.f32.tf32.tf32.f32 "
                 "{%0,%1,%2,%3},{%4,%5,%6,%7},{%8,%9},{%0,%1,%2,%3};"
                 : "+f"(c[0]), "+f"(c[1]), "+f"(c[2]), "+f"(c[3])
                 : "r"(a0), "r"(a1), "r"(a2), "r"(a3), "r"(b0), "r"(b1));
}

// ============================================================================
// GEMM (single TF32):  C[M,N] = A[M,K] * B[N,K]^T  (+ optional bias over N)
// 128x128 CTA tile, KT=16, 8 warps of 64x32, m16n8k8 tf32 mma.
// Row stride 20 => fragment LDS bank = (20g + i) mod 32 : conflict-free.
// ============================================================================
#define KT 16

__global__ __launch_bounds__(256)
void gemm_tc(const float* __restrict__ A, const float* __restrict__ B,
             float* __restrict__ C, int M, int N, int K,
             const float* __restrict__ bias)
{
    __shared__ __align__(16) unsigned As[128][20];
    __shared__ __align__(16) unsigned Bs[128][20];

    const int tid   = threadIdx.x;
    const int wid   = tid >> 5;
    const int lane  = tid & 31;
    const int g     = lane >> 2;          // 0..7
    const int i     = lane & 3;           // 0..3
    const int warpM = wid & 1;
    const int warpN = wid >> 1;
    const int mbase = warpM * 64;
    const int nbase = warpN * 32;
    const int m0    = blockIdx.y << 7;
    const int n0    = blockIdx.x << 7;

    const int lrow  = tid >> 1;           // 0..127
    const int lcol  = (tid & 1) << 3;     // 0 or 8
    const float* aptr = A + (size_t)(m0 + lrow) * K + lcol;
    const float* bptr = B + (size_t)(n0 + lrow) * K + lcol;

    float c[4][4][4];
#pragma unroll
    for (int mf = 0; mf < 4; mf++)
#pragma unroll
        for (int nf = 0; nf < 4; nf++)
#pragma unroll
            for (int t = 0; t < 4; t++) c[mf][nf][t] = 0.f;

    const int nstages = K / KT;  // 32

    float4 ra0 = *(const float4*)(aptr);
    float4 ra1 = *(const float4*)(aptr + 4);
    float4 rb0 = *(const float4*)(bptr);
    float4 rb1 = *(const float4*)(bptr + 4);

    for (int s = 0; s < nstages; s++) {
        // store stage s (convert once here)
        {
            uint4 t0 = make_uint4(f2tf(ra0.x), f2tf(ra0.y), f2tf(ra0.z), f2tf(ra0.w));
            uint4 t1 = make_uint4(f2tf(ra1.x), f2tf(ra1.y), f2tf(ra1.z), f2tf(ra1.w));
            *(uint4*)&As[lrow][lcol]     = t0;
            *(uint4*)&As[lrow][lcol + 4] = t1;
            uint4 u0 = make_uint4(f2tf(rb0.x), f2tf(rb0.y), f2tf(rb0.z), f2tf(rb0.w));
            uint4 u1 = make_uint4(f2tf(rb1.x), f2tf(rb1.y), f2tf(rb1.z), f2tf(rb1.w));
            *(uint4*)&Bs[lrow][lcol]     = u0;
            *(uint4*)&Bs[lrow][lcol + 4] = u1;
        }
        __syncthreads();

        // prefetch stage s+1
        if (s + 1 < nstages) {
            int ko = (s + 1) * KT;
            ra0 = *(const float4*)(aptr + ko);
            ra1 = *(const float4*)(aptr + ko + 4);
            rb0 = *(const float4*)(bptr + ko);
            rb1 = *(const float4*)(bptr + ko + 4);
        }

        // compute 2 ksteps of 8
#pragma unroll
        for (int ks = 0; ks < 2; ks++) {
            const int k0i = (ks << 3) + i;
            unsigned a[4][4];
            unsigned b[4][2];
#pragma unroll
            for (int mf = 0; mf < 4; mf++) {
                int r = mbase + (mf << 4);
                a[mf][0] = As[r + g    ][k0i];
                a[mf][1] = As[r + g + 8][k0i];
                a[mf][2] = As[r + g    ][k0i + 4];
                a[mf][3] = As[r + g + 8][k0i + 4];
            }
#pragma unroll
            for (int nf = 0; nf < 4; nf++) {
                int r = nbase + (nf << 3) + g;
                b[nf][0] = Bs[r][k0i];
                b[nf][1] = Bs[r][k0i + 4];
            }
#pragma unroll
            for (int mf = 0; mf < 4; mf++)
#pragma unroll
                for (int nf = 0; nf < 4; nf++)
                    mma8(c[mf][nf], a[mf][0], a[mf][1], a[mf][2], a[mf][3],
                                    b[nf][0], b[nf][1]);
        }
        __syncthreads();
    }

    // epilogue
#pragma unroll
    for (int mf = 0; mf < 4; mf++) {
        int r0 = m0 + mbase + (mf << 4) + g;
        int r1 = r0 + 8;
#pragma unroll
        for (int nf = 0; nf < 4; nf++) {
            int col = n0 + nbase + (nf << 3) + (i << 1);
            float bx = bias ? bias[col]     : 0.f;
            float by = bias ? bias[col + 1] : 0.f;
            float2 v0 = make_float2(c[mf][nf][0] + bx, c[mf][nf][1] + by);
            float2 v1 = make_float2(c[mf][nf][2] + bx, c[mf][nf][3] + by);
            *(float2*)&C[(size_t)r0 * N + col] = v0;
            *(float2*)&C[(size_t)r1 * N + col] = v1;
        }
    }
}

// ============================================================================
// LePE depthwise 5x5 conv, smem-tiled.
// CTA = (64-channel group, output row i, batch b).  smem holds 5 input rows
// for those channels; each x element is read from gmem once per output row.
// ============================================================================
__global__ __launch_bounds__(256)
void lepe_conv(const float* __restrict__ x, const float* __restrict__ w,
               const float* __restrict__ bias, float* __restrict__ y)
{
    __shared__ float xs[5][32][64];   // [row][j][c] : c spans banks, conflict-free

    const int c  = threadIdx.x & 63;        // 0..63
    const int jt = threadIdx.x >> 6;        // 0..3
    const int cg = blockIdx.x;              // 0..7  (channel group)
    const int i  = blockIdx.y;              // 0..31 (output row)
    const int b  = blockIdx.z;              // 0..7
    const int cc = cg * 64 + c;

    // load 5 input rows (zero padded)
#pragma unroll
    for (int r = 0; r < 5; r++) {
        int ii = i + r - 2;
        bool ok = (ii >= 0 && ii < 32);
        const float* src = x + ((size_t)((b * 32 + ii) * 32)) * DIMC + cc;
#pragma unroll
        for (int l = 0; l < 8; l++) {
            int jj = jt + (l << 2);
            xs[r][jj][c] = ok ? src[(size_t)jj * DIMC] : 0.f;
        }
    }

    float wr[25];
#pragma unroll
    for (int t = 0; t < 25; t++) wr[t] = w[cc * 25 + t];
    const float bv = bias[cc];

    __syncthreads();

#pragma unroll
    for (int l = 0; l < 8; l++) {
        int jj = jt + (l << 2);
        float acc = bv;
#pragma unroll
        for (int u = 0; u < 5; u++)
#pragma unroll
            for (int v = 0; v < 5; v++) {
                int jv = jj + v - 2;
                if (jv >= 0 && jv < 32)
                    acc += xs[u][jv][c] * wr[u * 5 + v];
            }
        y[((size_t)(b * 1024 + i * 32 + jj)) * DIMC + cc] = acc;
    }
}

// ============================================================================
// Attention (tf32 tensor-core flash).  CTA = (64 q-rows, head, batch).
// ============================================================================
#define QB 64
#define KB 64

__global__ __launch_bounds__(128)
void attn_tc(const float* __restrict__ qkv, float* __restrict__ y)
{
    __shared__ __align__(16) unsigned Qs[QB][36];
    __shared__ __align__(16) unsigned Ks[KB][36];
    __shared__ __align__(16) unsigned Vs[KB][36];
    __shared__ __align__(16) unsigned Ps[QB][68];

    const int tid  = threadIdx.x;
    const int warp = tid >> 5;
    const int lane = tid & 31;
    const int g    = lane >> 2;
    const int i    = lane & 3;
    const int w16  = warp << 4;

    const int qb0 = blockIdx.x * QB;
    const int h   = blockIdx.y;
    const int b   = blockIdx.z;
    const float scale = 0.17677669529663687f;  // 32^-0.5

    const size_t rowstride = 3 * DIMC;
    const size_t base  = (size_t)b * SEQ * rowstride + h * HD;
    const size_t kbase = base + DIMC;
    const size_t vbase = base + 2 * DIMC;

#pragma unroll
    for (int l = 0; l < 4; l++) {
        int fi = tid + (l << 7);
        int r  = fi >> 3;
        int d4 = (fi & 7) << 2;
        float4 v = *(const float4*)(qkv + base + (size_t)(qb0 + r) * rowstride + d4);
        uint4 t;
        t.x = f2tf(v.x * scale); t.y = f2tf(v.y * scale);
        t.z = f2tf(v.z * scale); t.w = f2tf(v.w * scale);
        *(uint4*)&Qs[r][d4] = t;
    }
    __syncthreads();

    unsigned qa[4][4];
#pragma unroll
    for (int ks = 0; ks < 4; ks++) {
        int kc = (ks << 3) + i;
        qa[ks][0] = Qs[w16 + g    ][kc];
        qa[ks][1] = Qs[w16 + g + 8][kc];
        qa[ks][2] = Qs[w16 + g    ][kc + 4];
        qa[ks][3] = Qs[w16 + g + 8][kc + 4];
    }

    float o[4][4];
#pragma unroll
    for (int nf = 0; nf < 4; nf++)
#pragma unroll
        for (int t = 0; t < 4; t++) o[nf][t] = 0.f;
    float m0r = -CUDART_INF_F, m1r = -CUDART_INF_F;
    float l0r = 0.f, l1r = 0.f;

    for (int kt = 0; kt < SEQ / KB; kt++) {
        __syncthreads();
#pragma unroll
        for (int l = 0; l < 4; l++) {
            int fi = tid + (l << 7);
            int r  = fi >> 3;
            int d4 = (fi & 7) << 2;
            size_t roff = (size_t)(kt * KB + r) * rowstride + d4;
            float4 kv = *(const float4*)(qkv + kbase + roff);
            uint4 tk;
            tk.x = f2tf(kv.x); tk.y = f2tf(kv.y); tk.z = f2tf(kv.z); tk.w = f2tf(kv.w);
            *(uint4*)&Ks[r][d4] = tk;
            float4 vv = *(const float4*)(qkv + vbase + roff);
            uint4 tv;
            tv.x = f2tf(vv.x); tv.y = f2tf(vv.y); tv.z = f2tf(vv.z); tv.w = f2tf(vv.w);
            *(uint4*)&Vs[r][d4] = tv;
        }
        __syncthreads();

        float s[8][4];
#pragma unroll
        for (int nf = 0; nf < 8; nf++) {
            s[nf][0] = 0.f; s[nf][1] = 0.f; s[nf][2] = 0.f; s[nf][3] = 0.f;
        }
#pragma unroll
        for (int nf = 0; nf < 8; nf++) {
            int nr = (nf << 3) + g;
#pragma unroll
            for (int ks = 0; ks < 4; ks++) {
                int kc = (ks << 3) + i;
                mma8(s[nf], qa[ks][0], qa[ks][1], qa[ks][2], qa[ks][3],
                     Ks[nr][kc], Ks[nr][kc + 4]);
            }
        }

        float mx0 = -CUDART_INF_F, mx1 = -CUDART_INF_F;
#pragma unroll
        for (int nf = 0; nf < 8; nf++) {
            mx0 = fmaxf(mx0, fmaxf(s[nf][0], s[nf][1]));
            mx1 = fmaxf(mx1, fmaxf(s[nf][2], s[nf][3]));
        }
        mx0 = fmaxf(mx0, __shfl_xor_sync(0xffffffffu, mx0, 1));
        mx0 = fmaxf(mx0, __shfl_xor_sync(0xffffffffu, mx0, 2));
        mx1 = fmaxf(mx1, __shfl_xor_sync(0xffffffffu, mx1, 1));
        mx1 = fmaxf(mx1, __shfl_xor_sync(0xffffffffu, mx1, 2));

        float mn0 = fmaxf(m0r, mx0);
        float mn1 = fmaxf(m1r, mx1);
        float cor0 = __expf(m0r - mn0);
        float cor1 = __expf(m1r - mn1);
        m0r = mn0; m1r = mn1;

        float ps0 = 0.f, ps1 = 0.f;
#pragma unroll
        for (int nf = 0; nf < 8; nf++) {
            float p0 = __expf(s[nf][0] - mn0);
            float p1 = __expf(s[nf][1] - mn0);
            float p2 = __expf(s[nf][2] - mn1);
            float p3 = __expf(s[nf][3] - mn1);
            ps0 += p0 + p1;
            ps1 += p2 + p3;
            int col = (nf << 3) + (i << 1);
            *(uint2*)&Ps[w16 + g    ][col] = make_uint2(f2tf(p0), f2tf(p1));
            *(uint2*)&Ps[w16 + g + 8][col] = make_uint2(f2tf(p2), f2tf(p3));
        }
        ps0 += __shfl_xor_sync(0xffffffffu, ps0, 1);
        ps0 += __shfl_xor_sync(0xffffffffu, ps0, 2);
        ps1 += __shfl_xor_sync(0xffffffffu, ps1, 1);
        ps1 += __shfl_xor_sync(0xffffffffu, ps1, 2);
        l0r = l0r * cor0 + ps0;
        l1r = l1r * cor1 + ps1;

#pragma unroll
        for (int nf = 0; nf < 4; nf++) {
            o[nf][0] *= cor0; o[nf][1] *= cor0;
            o[nf][2] *= cor1; o[nf][3] *= cor1;
        }
        __syncwarp();

#pragma unroll
        for (int ks = 0; ks < 8; ks++) {
            int kc = (ks << 3) + i;
            unsigned pa0 = Ps[w16 + g    ][kc];
            unsigned pa1 = Ps[w16 + g + 8][kc];
            unsigned pa2 = Ps[w16 + g    ][kc + 4];
            unsigned pa3 = Ps[w16 + g + 8][kc + 4];
            int kr0 = (ks << 3) + i;
#pragma unroll
            for (int nf = 0; nf < 4; nf++) {
                int nc = (nf << 3) + g;
                mma8(o[nf], pa0, pa1, pa2, pa3, Vs[kr0][nc], Vs[kr0 + 4][nc]);
            }
        }
    }

    float inv0 = 1.f / l0r;
    float inv1 = 1.f / l1r;
    int r0 = b * SEQ + qb0 + w16 + g;
    int r1 = r0 + 8;
#pragma unroll
    for (int nf = 0; nf < 4; nf++) {
        int col = h * HD + (nf << 3) + (i << 1);
        size_t i00 = (size_t)r0 * DIMC + col;
        size_t i10 = (size_t)r1 * DIMC + col;
        y[i00]     += o[nf][0] * inv0;
        y[i00 + 1] += o[nf][1] * inv0;
        y[i10]     += o[nf][2] * inv1;
        y[i10 + 1] += o[nf][3] * inv1;
    }
}

// ============================================================================
// launch
// ============================================================================
extern "C" void kernel_launch(void* const* d_in, const int* in_sizes, int n_in,
                              void* d_out, int out_size)
{
    const float* x      = (const float*)d_in[0];
    const float* w_qkv  = (const float*)d_in[1];
    const float* w_proj = (const float*)d_in[2];
    const float* b_proj = (const float*)d_in[3];
    const float* w_lepe = (const float*)d_in[4];
    const float* b_lepe = (const float*)d_in[5];
    float* out = (float*)d_out;

    void* p_qkv = nullptr;
    void* p_y   = nullptr;
    cudaGetSymbolAddress(&p_qkv, g_qkv);
    cudaGetSymbolAddress(&p_y,   g_y);
    float* qkv = (float*)p_qkv;
    float* y   = (float*)p_y;

    // 1) QKV GEMM: [8192,1536] = x[8192,512] @ w_qkv[1536,512]^T
    gemm_tc<<<dim3(3 * DIMC / 128, MTOT / 128), 256>>>(x, w_qkv, qkv,
                                                       MTOT, 3 * DIMC, DIMC, nullptr);
    // 2) LePE conv -> y (smem tiled)
    lepe_conv<<<dim3(8, 32, BATCH), 256>>>(x, w_lepe, b_lepe, y);
    // 3) attention, y += attn_out
    attn_tc<<<dim3(SEQ / QB, HEADS, BATCH), 128>>>(qkv, y);
    // 4) proj: out = y @ w_proj^T + b_proj
    gemm_tc<<<dim3(DIMC / 128, MTOT / 128), 256>>>(y, w_proj, out,
                                                   MTOT, DIMC, DIMC, b_proj);
}

// round 7
// speedup vs baseline: 2.8661x; 1.0297x over previous
#include <cuda_runtime.h>
#include <math_constants.h>

#define DIMC   512
#define HEADS  16
#define HD     32
#define BATCH  8
#define SEQ    1024
#define MTOT   (BATCH*SEQ)   // 8192

// ---------------- scratch (no allocations allowed) ----------------
__device__ float g_qkv[(size_t)MTOT * 3 * DIMC];  // [8192][1536]
__device__ float g_y  [(size_t)MTOT * DIMC];      // [8192][512]  (lepe + attn out)

// ---------------- helpers ----------------
__device__ __forceinline__ unsigned f2tf(float x) {
    unsigned r; asm("cvt.rna.tf32.f32 %0, %1;" : "=r"(r) : "f"(x)); return r;
}
__device__ __forceinline__ void mma8(float* c,
                                     unsigned a0, unsigned a1, unsigned a2, unsigned a3,
                                     unsigned b0, unsigned b1) {
    asm volatile("mma.sync.aligned.m16n8k8.row.col.f32.tf32.tf32.f32 "
                 "{%0,%1,%2,%3},{%4,%5,%6,%7},{%8,%9},{%0,%1,%2,%3};"
                 : "+f"(c[0]), "+f"(c[1]), "+f"(c[2]), "+f"(c[3])
                 : "r"(a0), "r"(a1), "r"(a2), "r"(a3), "r"(b0), "r"(b1));
}

// ============================================================================
// GEMM (single TF32, double-buffered):  C[M,N] = A[M,K]*B[N,K]^T (+bias)
// 128x128 CTA, KT=16, 8 warps of 64x32, one __syncthreads per stage.
// ============================================================================
#define KT 16

__global__ __launch_bounds__(256)
void gemm_tc(const float* __restrict__ A, const float* __restrict__ B,
             float* __restrict__ C, int M, int N, int K,
             const float* __restrict__ bias)
{
    __shared__ __align__(16) unsigned As[2][128][20];
    __shared__ __align__(16) unsigned Bs[2][128][20];

    const int tid   = threadIdx.x;
    const int wid   = tid >> 5;
    const int lane  = tid & 31;
    const int g     = lane >> 2;
    const int i     = lane & 3;
    const int mbase = (wid & 1) * 64;
    const int nbase = (wid >> 1) * 32;
    const int m0    = blockIdx.y << 7;
    const int n0    = blockIdx.x << 7;

    const int lrow  = tid >> 1;
    const int lcol  = (tid & 1) << 3;
    const float* aptr = A + (size_t)(m0 + lrow) * K + lcol;
    const float* bptr = B + (size_t)(n0 + lrow) * K + lcol;

    float c[4][4][4];
#pragma unroll
    for (int mf = 0; mf < 4; mf++)
#pragma unroll
        for (int nf = 0; nf < 4; nf++)
#pragma unroll
            for (int t = 0; t < 4; t++) c[mf][nf][t] = 0.f;

    const int nstages = K / KT;

    float4 ra0 = *(const float4*)(aptr);
    float4 ra1 = *(const float4*)(aptr + 4);
    float4 rb0 = *(const float4*)(bptr);
    float4 rb1 = *(const float4*)(bptr + 4);

    // store stage 0 into buffer 0
    {
        *(uint4*)&As[0][lrow][lcol]   = make_uint4(f2tf(ra0.x), f2tf(ra0.y), f2tf(ra0.z), f2tf(ra0.w));
        *(uint4*)&As[0][lrow][lcol+4] = make_uint4(f2tf(ra1.x), f2tf(ra1.y), f2tf(ra1.z), f2tf(ra1.w));
        *(uint4*)&Bs[0][lrow][lcol]   = make_uint4(f2tf(rb0.x), f2tf(rb0.y), f2tf(rb0.z), f2tf(rb0.w));
        *(uint4*)&Bs[0][lrow][lcol+4] = make_uint4(f2tf(rb1.x), f2tf(rb1.y), f2tf(rb1.z), f2tf(rb1.w));
    }
    __syncthreads();

    for (int s = 0; s < nstages; s++) {
        const int cur = s & 1;
        const int nxt = cur ^ 1;

        // prefetch stage s+1 (issued before compute so latency overlaps MMAs)
        if (s + 1 < nstages) {
            int ko = (s + 1) * KT;
            ra0 = *(const float4*)(aptr + ko);
            ra1 = *(const float4*)(aptr + ko + 4);
            rb0 = *(const float4*)(bptr + ko);
            rb1 = *(const float4*)(bptr + ko + 4);
        }

        // compute 2 ksteps of 8 from buffer cur
#pragma unroll
        for (int ks = 0; ks < 2; ks++) {
            const int k0i = (ks << 3) + i;
            unsigned a[4][4];
            unsigned b[4][2];
#pragma unroll
            for (int mf = 0; mf < 4; mf++) {
                int r = mbase + (mf << 4);
                a[mf][0] = As[cur][r + g    ][k0i];
                a[mf][1] = As[cur][r + g + 8][k0i];
                a[mf][2] = As[cur][r + g    ][k0i + 4];
                a[mf][3] = As[cur][r + g + 8][k0i + 4];
            }
#pragma unroll
            for (int nf = 0; nf < 4; nf++) {
                int r = nbase + (nf << 3) + g;
                b[nf][0] = Bs[cur][r][k0i];
                b[nf][1] = Bs[cur][r][k0i + 4];
            }
#pragma unroll
            for (int mf = 0; mf < 4; mf++)
#pragma unroll
                for (int nf = 0; nf < 4; nf++)
                    mma8(c[mf][nf], a[mf][0], a[mf][1], a[mf][2], a[mf][3],
                                    b[nf][0], b[nf][1]);
        }

        // store stage s+1 into the other buffer
        if (s + 1 < nstages) {
            *(uint4*)&As[nxt][lrow][lcol]   = make_uint4(f2tf(ra0.x), f2tf(ra0.y), f2tf(ra0.z), f2tf(ra0.w));
            *(uint4*)&As[nxt][lrow][lcol+4] = make_uint4(f2tf(ra1.x), f2tf(ra1.y), f2tf(ra1.z), f2tf(ra1.w));
            *(uint4*)&Bs[nxt][lrow][lcol]   = make_uint4(f2tf(rb0.x), f2tf(rb0.y), f2tf(rb0.z), f2tf(rb0.w));
            *(uint4*)&Bs[nxt][lrow][lcol+4] = make_uint4(f2tf(rb1.x), f2tf(rb1.y), f2tf(rb1.z), f2tf(rb1.w));
        }
        __syncthreads();
    }

    // epilogue
#pragma unroll
    for (int mf = 0; mf < 4; mf++) {
        int r0 = m0 + mbase + (mf << 4) + g;
        int r1 = r0 + 8;
#pragma unroll
        for (int nf = 0; nf < 4; nf++) {
            int col = n0 + nbase + (nf << 3) + (i << 1);
            float bx = bias ? bias[col]     : 0.f;
            float by = bias ? bias[col + 1] : 0.f;
            *(float2*)&C[(size_t)r0 * N + col] = make_float2(c[mf][nf][0] + bx, c[mf][nf][1] + by);
            *(float2*)&C[(size_t)r1 * N + col] = make_float2(c[mf][nf][2] + bx, c[mf][nf][3] + by);
        }
    }
}

// ============================================================================
// LePE depthwise 5x5 conv, smem-tiled.
// ============================================================================
__global__ __launch_bounds__(256)
void lepe_conv(const float* __restrict__ x, const float* __restrict__ w,
               const float* __restrict__ bias, float* __restrict__ y)
{
    __shared__ float xs[5][32][64];

    const int c  = threadIdx.x & 63;
    const int jt = threadIdx.x >> 6;
    const int cg = blockIdx.x;
    const int i  = blockIdx.y;
    const int b  = blockIdx.z;
    const int cc = cg * 64 + c;

#pragma unroll
    for (int r = 0; r < 5; r++) {
        int ii = i + r - 2;
        bool ok = (ii >= 0 && ii < 32);
        const float* src = x + ((size_t)((b * 32 + ii) * 32)) * DIMC + cc;
#pragma unroll
        for (int l = 0; l < 8; l++) {
            int jj = jt + (l << 2);
            xs[r][jj][c] = ok ? src[(size_t)jj * DIMC] : 0.f;
        }
    }

    float wr[25];
#pragma unroll
    for (int t = 0; t < 25; t++) wr[t] = w[cc * 25 + t];
    const float bv = bias[cc];

    __syncthreads();

#pragma unroll
    for (int l = 0; l < 8; l++) {
        int jj = jt + (l << 2);
        float acc = bv;
#pragma unroll
        for (int u = 0; u < 5; u++)
#pragma unroll
            for (int v = 0; v < 5; v++) {
                int jv = jj + v - 2;
                if (jv >= 0 && jv < 32)
                    acc += xs[u][jv][c] * wr[u * 5 + v];
            }
        y[((size_t)(b * 1024 + i * 32 + jj)) * DIMC + cc] = acc;
    }
}

// ============================================================================
// Attention (tf32 flash).  CTA = 128 q-rows x (head, batch), 8 warps.
// KB=32 K/V tiles, double-buffered, Q fragments direct from gmem.
// One __syncthreads per tile.
// ============================================================================
#define QB 128
#define KB 32

__global__ __launch_bounds__(256)
void attn_tc(const float* __restrict__ qkv, float* __restrict__ y)
{
    __shared__ __align__(16) unsigned Ks[2][KB][36];
    __shared__ __align__(16) unsigned Vs[2][KB][36];
    __shared__ __align__(16) unsigned Ps[QB][36];

    const int tid  = threadIdx.x;
    const int warp = tid >> 5;
    const int lane = tid & 31;
    const int g    = lane >> 2;
    const int i    = lane & 3;
    const int w16  = warp << 4;

    const int qb0 = blockIdx.x * QB;
    const int h   = blockIdx.y;
    const int b   = blockIdx.z;
    const float scale = 0.17677669529663687f;  // 32^-0.5

    const size_t rowstride = 3 * DIMC;
    const size_t base  = (size_t)b * SEQ * rowstride + h * HD;
    const size_t kbase = base + DIMC;
    const size_t vbase = base + 2 * DIMC;

    // ---- Q fragments straight from gmem (once per CTA) ----
    unsigned qa[4][4];
    {
        const float* q0 = qkv + base + (size_t)(qb0 + w16 + g) * rowstride;
        const float* q1 = q0 + 8 * rowstride;
#pragma unroll
        for (int ks = 0; ks < 4; ks++) {
            int kc = (ks << 3) + i;
            qa[ks][0] = f2tf(q0[kc]     * scale);
            qa[ks][1] = f2tf(q1[kc]     * scale);
            qa[ks][2] = f2tf(q0[kc + 4] * scale);
            qa[ks][3] = f2tf(q1[kc + 4] * scale);
        }
    }

    // loader mapping: one float4 of K and one of V per thread per tile
    const int lr = tid >> 3;            // 0..31 (tile row)
    const int ld = (tid & 7) << 2;      // 0,4,..,28
    const float* kp = qkv + kbase + (size_t)lr * rowstride + ld;
    const float* vp = qkv + vbase + (size_t)lr * rowstride + ld;

    float4 rk = *(const float4*)(kp);
    float4 rv = *(const float4*)(vp);
    *(uint4*)&Ks[0][lr][ld] = make_uint4(f2tf(rk.x), f2tf(rk.y), f2tf(rk.z), f2tf(rk.w));
    *(uint4*)&Vs[0][lr][ld] = make_uint4(f2tf(rv.x), f2tf(rv.y), f2tf(rv.z), f2tf(rv.w));
    __syncthreads();

    float o[4][4];
#pragma unroll
    for (int nf = 0; nf < 4; nf++)
#pragma unroll
        for (int t = 0; t < 4; t++) o[nf][t] = 0.f;
    float m0r = -CUDART_INF_F, m1r = -CUDART_INF_F;
    float l0r = 0.f, l1r = 0.f;

    const int NT = SEQ / KB;   // 32

    for (int kt = 0; kt < NT; kt++) {
        const int cur = kt & 1;
        const int nxt = cur ^ 1;

        // prefetch next tile (gmem latency overlaps compute below)
        if (kt + 1 < NT) {
            size_t off = (size_t)(kt + 1) * KB * rowstride;
            rk = *(const float4*)(kp + off);
            rv = *(const float4*)(vp + off);
        }

        // ---- S = Q K^T : 4 n-frags of 8 cols ----
        float s[4][4];
#pragma unroll
        for (int nf = 0; nf < 4; nf++) {
            s[nf][0] = 0.f; s[nf][1] = 0.f; s[nf][2] = 0.f; s[nf][3] = 0.f;
        }
#pragma unroll
        for (int nf = 0; nf < 4; nf++) {
            int nr = (nf << 3) + g;
#pragma unroll
            for (int ks = 0; ks < 4; ks++) {
                int kc = (ks << 3) + i;
                mma8(s[nf], qa[ks][0], qa[ks][1], qa[ks][2], qa[ks][3],
                     Ks[cur][nr][kc], Ks[cur][nr][kc + 4]);
            }
        }

        // ---- online softmax (rows g and g+8 of this warp) ----
        float mx0 = fmaxf(fmaxf(s[0][0], s[0][1]), fmaxf(s[1][0], s[1][1]));
        float mx1 = fmaxf(fmaxf(s[0][2], s[0][3]), fmaxf(s[1][2], s[1][3]));
        mx0 = fmaxf(mx0, fmaxf(fmaxf(s[2][0], s[2][1]), fmaxf(s[3][0], s[3][1])));
        mx1 = fmaxf(mx1, fmaxf(fmaxf(s[2][2], s[2][3]), fmaxf(s[3][2], s[3][3])));
        mx0 = fmaxf(mx0, __shfl_xor_sync(0xffffffffu, mx0, 1));
        mx0 = fmaxf(mx0, __shfl_xor_sync(0xffffffffu, mx0, 2));
        mx1 = fmaxf(mx1, __shfl_xor_sync(0xffffffffu, mx1, 1));
        mx1 = fmaxf(mx1, __shfl_xor_sync(0xffffffffu, mx1, 2));

        float mn0 = fmaxf(m0r, mx0);
        float mn1 = fmaxf(m1r, mx1);
        float cor0 = __expf(m0r - mn0);
        float cor1 = __expf(m1r - mn1);
        m0r = mn0; m1r = mn1;

        float ps0 = 0.f, ps1 = 0.f;
#pragma unroll
        for (int nf = 0; nf < 4; nf++) {
            float p0 = __expf(s[nf][0] - mn0);
            float p1 = __expf(s[nf][1] - mn0);
            float p2 = __expf(s[nf][2] - mn1);
            float p3 = __expf(s[nf][3] - mn1);
            ps0 += p0 + p1;
            ps1 += p2 + p3;
            int col = (nf << 3) + (i << 1);
            *(uint2*)&Ps[w16 + g    ][col] = make_uint2(f2tf(p0), f2tf(p1));
            *(uint2*)&Ps[w16 + g + 8][col] = make_uint2(f2tf(p2), f2tf(p3));
        }
        ps0 += __shfl_xor_sync(0xffffffffu, ps0, 1);
        ps0 += __shfl_xor_sync(0xffffffffu, ps0, 2);
        ps1 += __shfl_xor_sync(0xffffffffu, ps1, 1);
        ps1 += __shfl_xor_sync(0xffffffffu, ps1, 2);
        l0r = l0r * cor0 + ps0;
        l1r = l1r * cor1 + ps1;

#pragma unroll
        for (int nf = 0; nf < 4; nf++) {
            o[nf][0] *= cor0; o[nf][1] *= cor0;
            o[nf][2] *= cor1; o[nf][3] *= cor1;
        }
        __syncwarp();   // Ps rows of this warp visible to its own lanes

        // ---- O += P * V : k=32 (4 ksteps), n=32 (4 nfrags) ----
#pragma unroll
        for (int ks = 0; ks < 4; ks++) {
            int kc = (ks << 3) + i;
            unsigned pa0 = Ps[w16 + g    ][kc];
            unsigned pa1 = Ps[w16 + g + 8][kc];
            unsigned pa2 = Ps[w16 + g    ][kc + 4];
            unsigned pa3 = Ps[w16 + g + 8][kc + 4];
#pragma unroll
            for (int nf = 0; nf < 4; nf++) {
                int nc = (nf << 3) + g;
                mma8(o[nf], pa0, pa1, pa2, pa3,
                     Vs[cur][kc][nc], Vs[cur][kc + 4][nc]);
            }
        }

        // store next tile into other buffer
        if (kt + 1 < NT) {
            *(uint4*)&Ks[nxt][lr][ld] = make_uint4(f2tf(rk.x), f2tf(rk.y), f2tf(rk.z), f2tf(rk.w));
            *(uint4*)&Vs[nxt][lr][ld] = make_uint4(f2tf(rv.x), f2tf(rv.y), f2tf(rv.z), f2tf(rv.w));
        }
        __syncthreads();
    }

    // ---- finalize: y += O / l ----
    float inv0 = 1.f / l0r;
    float inv1 = 1.f / l1r;
    int r0 = b * SEQ + qb0 + w16 + g;
    int r1 = r0 + 8;
#pragma unroll
    for (int nf = 0; nf < 4; nf++) {
        int col = h * HD + (nf << 3) + (i << 1);
        size_t i00 = (size_t)r0 * DIMC + col;
        size_t i10 = (size_t)r1 * DIMC + col;
        y[i00]     += o[nf][0] * inv0;
        y[i00 + 1] += o[nf][1] * inv0;
        y[i10]     += o[nf][2] * inv1;
        y[i10 + 1] += o[nf][3] * inv1;
    }
}

// ============================================================================
// launch
// ============================================================================
extern "C" void kernel_launch(void* const* d_in, const int* in_sizes, int n_in,
                              void* d_out, int out_size)
{
    const float* x      = (const float*)d_in[0];
    const float* w_qkv  = (const float*)d_in[1];
    const float* w_proj = (const float*)d_in[2];
    const float* b_proj = (const float*)d_in[3];
    const float* w_lepe = (const float*)d_in[4];
    const float* b_lepe = (const float*)d_in[5];
    float* out = (float*)d_out;

    void* p_qkv = nullptr;
    void* p_y   = nullptr;
    cudaGetSymbolAddress(&p_qkv, g_qkv);
    cudaGetSymbolAddress(&p_y,   g_y);
    float* qkv = (float*)p_qkv;
    float* y   = (float*)p_y;

    // 1) QKV GEMM: [8192,1536] = x[8192,512] @ w_qkv[1536,512]^T
    gemm_tc<<<dim3(3 * DIMC / 128, MTOT / 128), 256>>>(x, w_qkv, qkv,
                                                       MTOT, 3 * DIMC, DIMC, nullptr);
    // 2) LePE conv -> y (smem tiled)
    lepe_conv<<<dim3(8, 32, BATCH), 256>>>(x, w_lepe, b_lepe, y);
    // 3) attention, y += attn_out
    attn_tc<<<dim3(SEQ / QB, HEADS, BATCH), 256>>>(qkv, y);
    // 4) proj: out = y @ w_proj^T + b_proj
    gemm_tc<<<dim3(DIMC / 128, MTOT / 128), 256>>>(y, w_proj, out,
                                                   MTOT, DIMC, DIMC, b_proj);
}

// round 13
// speedup vs baseline: 2.9199x; 1.0188x over previous
#include <cuda_runtime.h>
#include <math_constants.h>
#include <cstdint>

#define DIMC   512
#define HEADS  16
#define HD     32
#define BATCH  8
#define SEQ    1024
#define MTOT   (BATCH*SEQ)   // 8192

// ---------------- scratch (no allocations allowed) ----------------
__device__ float g_qkv[(size_t)MTOT * 3 * DIMC];  // [8192][1536] (tf32-exact)
__device__ float g_y  [(size_t)MTOT * DIMC];      // [8192][512]  (lepe + attn out)
__device__ float g_xr [(size_t)MTOT * DIMC];      // x rounded to tf32
__device__ float g_yr [(size_t)MTOT * DIMC];      // y rounded to tf32
__device__ float g_wqr[(size_t)3 * DIMC * DIMC];  // w_qkv rounded
__device__ float g_wpr[(size_t)DIMC * DIMC];      // w_proj rounded

// ---------------- helpers ----------------
__device__ __forceinline__ unsigned f2tf(float x) {
    unsigned r; asm("cvt.rna.tf32.f32 %0, %1;" : "=r"(r) : "f"(x)); return r;
}
__device__ __forceinline__ void mma8(float* c,
                                     unsigned a0, unsigned a1, unsigned a2, unsigned a3,
                                     unsigned b0, unsigned b1) {
    asm volatile("mma.sync.aligned.m16n8k8.row.col.f32.tf32.tf32.f32 "
                 "{%0,%1,%2,%3},{%4,%5,%6,%7},{%8,%9},{%0,%1,%2,%3};"
                 : "+f"(c[0]), "+f"(c[1]), "+f"(c[2]), "+f"(c[3])
                 : "r"(a0), "r"(a1), "r"(a2), "r"(a3), "r"(b0), "r"(b1));
}
__device__ __forceinline__ uint32_t smem_u32(const void* p) {
    uint32_t a;
    asm("{ .reg .u64 t; cvta.to.shared.u64 t, %1; cvt.u32.u64 %0, t; }"
        : "=r"(a) : "l"(p));
    return a;
}
#define CP16(dst, src) \
    asm volatile("cp.async.cg.shared.global [%0], [%1], 16;" \
                 :: "r"(dst), "l"(src) : "memory")
#define CP_COMMIT() asm volatile("cp.async.commit_group;" ::: "memory")
#define CP_WAIT1()  asm volatile("cp.async.wait_group 1;" ::: "memory")
#define CP_WAIT0()  asm volatile("cp.async.wait_group 0;" ::: "memory")

// ============================================================================
// tf32 rounding pass (rna), float4-vectorized
// ============================================================================
__global__ __launch_bounds__(256)
void round_tf32_k(const float* __restrict__ src, float* __restrict__ dst, int n4)
{
    int idx = blockIdx.x * 256 + threadIdx.x;
    if (idx < n4) {
        float4 v = ((const float4*)src)[idx];
        float4 r;
        r.x = __uint_as_float(f2tf(v.x));
        r.y = __uint_as_float(f2tf(v.y));
        r.z = __uint_as_float(f2tf(v.z));
        r.w = __uint_as_float(f2tf(v.w));
        ((float4*)dst)[idx] = r;
    }
}

// ============================================================================
// GEMM (tf32 mma.sync + cp.async, 3-stage pipeline, 1 sync/stage):
// C[M,N] = A[M,K]*B[N,K]^T (+bias).  Inputs MUST be tf32-exact fp32.
// 128x128 CTA, KT=16, 8 warps of 64x32.
// ============================================================================
#define KT 16
#define G_STAGE_W 5120                 // words per stage: A 128*20 + B 128*20
#define G_SMEM    (3 * G_STAGE_W * 4)  // 61440 bytes

__global__ __launch_bounds__(256)
void gemm_tc(const float* __restrict__ A, const float* __restrict__ B,
             float* __restrict__ C, int M, int N, int K,
             const float* __restrict__ bias, int roundOut)
{
    extern __shared__ unsigned sm[];
    const uint32_t sbytes = smem_u32(sm);

    const int tid   = threadIdx.x;
    const int wid   = tid >> 5;
    const int lane  = tid & 31;
    const int g     = lane >> 2;
    const int i     = lane & 3;
    const int mbase = (wid & 1) * 64;
    const int nbase = (wid >> 1) * 32;
    const int m0    = blockIdx.y << 7;
    const int n0    = blockIdx.x << 7;

    const int lrow  = tid >> 1;          // 0..127
    const int lcol  = (tid & 1) << 3;    // 0 or 8
    const float* aptr = A + (size_t)(m0 + lrow) * K + lcol;
    const float* bptr = B + (size_t)(n0 + lrow) * K + lcol;
    const uint32_t dstA = sbytes + (uint32_t)(lrow * 20 + lcol) * 4;
    const uint32_t dstB = dstA + 2560u * 4;

    float c[4][4][4];
#pragma unroll
    for (int mf = 0; mf < 4; mf++)
#pragma unroll
        for (int nf = 0; nf < 4; nf++)
#pragma unroll
            for (int t = 0; t < 4; t++) c[mf][nf][t] = 0.f;

    const int nstages = K / KT;   // 32 for K=512

    auto issue = [&](int s) {
        uint32_t so = (uint32_t)(s % 3) * (G_STAGE_W * 4);
        const float* ap = aptr + s * KT;
        const float* bp = bptr + s * KT;
        CP16(dstA + so,      ap);
        CP16(dstA + so + 16, ap + 4);
        CP16(dstB + so,      bp);
        CP16(dstB + so + 16, bp + 4);
        CP_COMMIT();
    };

    issue(0);
    issue(1);

    for (int s = 0; s < nstages; s++) {
        if (s < nstages - 1) CP_WAIT1(); else CP_WAIT0();
        __syncthreads();
        if (s + 2 < nstages) issue(s + 2);

        const unsigned* As = sm + (s % 3) * G_STAGE_W;
        const unsigned* Bs = As + 2560;

#pragma unroll
        for (int ks = 0; ks < 2; ks++) {
            const int k0i = (ks << 3) + i;
            unsigned a[4][4];
            unsigned b[4][2];
#pragma unroll
            for (int mf = 0; mf < 4; mf++) {
                int r = mbase + (mf << 4);
                a[mf][0] = As[(r + g    ) * 20 + k0i];
                a[mf][1] = As[(r + g + 8) * 20 + k0i];
                a[mf][2] = As[(r + g    ) * 20 + k0i + 4];
                a[mf][3] = As[(r + g + 8) * 20 + k0i + 4];
            }
#pragma unroll
            for (int nf = 0; nf < 4; nf++) {
                int r = nbase + (nf << 3) + g;
                b[nf][0] = Bs[r * 20 + k0i];
                b[nf][1] = Bs[r * 20 + k0i + 4];
            }
#pragma unroll
            for (int mf = 0; mf < 4; mf++)
#pragma unroll
                for (int nf = 0; nf < 4; nf++)
                    mma8(c[mf][nf], a[mf][0], a[mf][1], a[mf][2], a[mf][3],
                                    b[nf][0], b[nf][1]);
        }
    }

    // epilogue
#pragma unroll
    for (int mf = 0; mf < 4; mf++) {
        int r0 = m0 + mbase + (mf << 4) + g;
        int r1 = r0 + 8;
#pragma unroll
        for (int nf = 0; nf < 4; nf++) {
            int col = n0 + nbase + (nf << 3) + (i << 1);
            float v0 = c[mf][nf][0], v1 = c[mf][nf][1];
            float v2 = c[mf][nf][2], v3 = c[mf][nf][3];
            if (bias) {
                float bx = bias[col], by = bias[col + 1];
                v0 += bx; v1 += by; v2 += bx; v3 += by;
            }
            if (roundOut) {
                v0 = __uint_as_float(f2tf(v0)); v1 = __uint_as_float(f2tf(v1));
                v2 = __uint_as_float(f2tf(v2)); v3 = __uint_as_float(f2tf(v3));
            }
            *(float2*)&C[(size_t)r0 * N + col] = make_float2(v0, v1);
            *(float2*)&C[(size_t)r1 * N + col] = make_float2(v2, v3);
        }
    }
}

// ============================================================================
// LePE depthwise 5x5 conv, smem-tiled (exact fp32).
// ============================================================================
__global__ __launch_bounds__(256)
void lepe_conv(const float* __restrict__ x, const float* __restrict__ w,
               const float* __restrict__ bias, float* __restrict__ y)
{
    __shared__ float xs[5][32][64];

    const int c  = threadIdx.x & 63;
    const int jt = threadIdx.x >> 6;
    const int cg = blockIdx.x;
    const int i  = blockIdx.y;
    const int b  = blockIdx.z;
    const int cc = cg * 64 + c;

#pragma unroll
    for (int r = 0; r < 5; r++) {
        int ii = i + r - 2;
        bool ok = (ii >= 0 && ii < 32);
        const float* src = x + ((size_t)((b * 32 + ii) * 32)) * DIMC + cc;
#pragma unroll
        for (int l = 0; l < 8; l++) {
            int jj = jt + (l << 2);
            xs[r][jj][c] = ok ? src[(size_t)jj * DIMC] : 0.f;
        }
    }

    float wr[25];
#pragma unroll
    for (int t = 0; t < 25; t++) wr[t] = w[cc * 25 + t];
    const float bv = bias[cc];

    __syncthreads();

#pragma unroll
    for (int l = 0; l < 8; l++) {
        int jj = jt + (l << 2);
        float acc = bv;
#pragma unroll
        for (int u = 0; u < 5; u++)
#pragma unroll
            for (int v = 0; v < 5; v++) {
                int jv = jj + v - 2;
                if (jv >= 0 && jv < 32)
                    acc += xs[u][jv][c] * wr[u * 5 + v];
            }
        y[((size_t)(b * 1024 + i * 32 + jj)) * DIMC + cc] = acc;
    }
}

// ============================================================================
// Attention (tf32 flash, mma.sync + cp.async K/V, 3-stage, 1 sync/tile).
// CTA = 128 q-rows x (head, batch), 8 warps.  qkv must be tf32-exact.
// ============================================================================
#define QB 128
#define KB 32
#define NT (SEQ / KB)   // 32

__global__ __launch_bounds__(256)
void attn_tc(const float* __restrict__ qkv, float* __restrict__ y)
{
    __shared__ __align__(16) unsigned Ks[3][KB][36];
    __shared__ __align__(16) unsigned Vs[3][KB][36];
    __shared__ __align__(16) unsigned Ps[QB][36];

    const int tid  = threadIdx.x;
    const int warp = tid >> 5;
    const int lane = tid & 31;
    const int g    = lane >> 2;
    const int i    = lane & 3;
    const int w16  = warp << 4;

    const int qb0 = blockIdx.x * QB;
    const int h   = blockIdx.y;
    const int b   = blockIdx.z;
    const float scale = 0.17677669529663687f;  // 32^-0.5

    const size_t rowstride = 3 * DIMC;
    const size_t base  = (size_t)b * SEQ * rowstride + h * HD;
    const size_t kbase = base + DIMC;
    const size_t vbase = base + 2 * DIMC;

    // ---- Q fragments straight from gmem (qkv is tf32-exact; rescale+round) ----
    unsigned qa[4][4];
    {
        const float* q0 = qkv + base + (size_t)(qb0 + w16 + g) * rowstride;
        const float* q1 = q0 + 8 * rowstride;
#pragma unroll
        for (int ks = 0; ks < 4; ks++) {
            int kc = (ks << 3) + i;
            qa[ks][0] = f2tf(q0[kc]     * scale);
            qa[ks][1] = f2tf(q1[kc]     * scale);
            qa[ks][2] = f2tf(q0[kc + 4] * scale);
            qa[ks][3] = f2tf(q1[kc + 4] * scale);
        }
    }

    // K/V loader: one float4 of K and one of V per thread per tile, via cp.async
    const int lr = tid >> 3;            // 0..31
    const int ld = (tid & 7) << 2;      // 0,4,..,28
    const float* kp = qkv + kbase + (size_t)lr * rowstride + ld;
    const float* vp = qkv + vbase + (size_t)lr * rowstride + ld;

    auto issue = [&](int t) {
        int st = t % 3;
        size_t off = (size_t)t * KB * rowstride;
        CP16(smem_u32(&Ks[st][lr][ld]), kp + off);
        CP16(smem_u32(&Vs[st][lr][ld]), vp + off);
        CP_COMMIT();
    };

    issue(0);
    issue(1);

    float o[4][4];
#pragma unroll
    for (int nf = 0; nf < 4; nf++)
#pragma unroll
        for (int t = 0; t < 4; t++) o[nf][t] = 0.f;
    float m0r = -CUDART_INF_F, m1r = -CUDART_INF_F;
    float l0r = 0.f, l1r = 0.f;

    for (int kt = 0; kt < NT; kt++) {
        const int cur = kt % 3;
        if (kt < NT - 1) CP_WAIT1(); else CP_WAIT0();
        __syncthreads();
        if (kt + 2 < NT) issue(kt + 2);

        // ---- S = Q K^T ----
        float s[4][4];
#pragma unroll
        for (int nf = 0; nf < 4; nf++) {
            s[nf][0] = 0.f; s[nf][1] = 0.f; s[nf][2] = 0.f; s[nf][3] = 0.f;
        }
#pragma unroll
        for (int nf = 0; nf < 4; nf++) {
            int nr = (nf << 3) + g;
#pragma unroll
            for (int ks = 0; ks < 4; ks++) {
                int kc = (ks << 3) + i;
                mma8(s[nf], qa[ks][0], qa[ks][1], qa[ks][2], qa[ks][3],
                     Ks[cur][nr][kc], Ks[cur][nr][kc + 4]);
            }
        }

        // ---- online softmax (rows g, g+8) ----
        float mx0 = fmaxf(fmaxf(s[0][0], s[0][1]), fmaxf(s[1][0], s[1][1]));
        float mx1 = fmaxf(fmaxf(s[0][2], s[0][3]), fmaxf(s[1][2], s[1][3]));
        mx0 = fmaxf(mx0, fmaxf(fmaxf(s[2][0], s[2][1]), fmaxf(s[3][0], s[3][1])));
        mx1 = fmaxf(mx1, fmaxf(fmaxf(s[2][2], s[2][3]), fmaxf(s[3][2], s[3][3])));
        mx0 = fmaxf(mx0, __shfl_xor_sync(0xffffffffu, mx0, 1));
        mx0 = fmaxf(mx0, __shfl_xor_sync(0xffffffffu, mx0, 2));
        mx1 = fmaxf(mx1, __shfl_xor_sync(0xffffffffu, mx1, 1));
        mx1 = fmaxf(mx1, __shfl_xor_sync(0xffffffffu, mx1, 2));

        float mn0 = fmaxf(m0r, mx0);
        float mn1 = fmaxf(m1r, mx1);
        float cor0 = __expf(m0r - mn0);
        float cor1 = __expf(m1r - mn1);
        m0r = mn0; m1r = mn1;

        float ps0 = 0.f, ps1 = 0.f;
#pragma unroll
        for (int nf = 0; nf < 4; nf++) {
            float p0 = __expf(s[nf][0] - mn0);
            float p1 = __expf(s[nf][1] - mn0);
            float p2 = __expf(s[nf][2] - mn1);
            float p3 = __expf(s[nf][3] - mn1);
            ps0 += p0 + p1;
            ps1 += p2 + p3;
            int col = (nf << 3) + (i << 1);
            *(uint2*)&Ps[w16 + g    ][col] = make_uint2(f2tf(p0), f2tf(p1));
            *(uint2*)&Ps[w16 + g + 8][col] = make_uint2(f2tf(p2), f2tf(p3));
        }
        ps0 += __shfl_xor_sync(0xffffffffu, ps0, 1);
        ps0 += __shfl_xor_sync(0xffffffffu, ps0, 2);
        ps1 += __shfl_xor_sync(0xffffffffu, ps1, 1);
        ps1 += __shfl_xor_sync(0xffffffffu, ps1, 2);
        l0r = l0r * cor0 + ps0;
        l1r = l1r * cor1 + ps1;

#pragma unroll
        for (int nf = 0; nf < 4; nf++) {
            o[nf][0] *= cor0; o[nf][1] *= cor0;
            o[nf][2] *= cor1; o[nf][3] *= cor1;
        }
        __syncwarp();   // own-warp Ps rows visible

        // ---- O += P * V ----
#pragma unroll
        for (int ks = 0; ks < 4; ks++) {
            int kc = (ks << 3) + i;
            unsigned pa0 = Ps[w16 + g    ][kc];
            unsigned pa1 = Ps[w16 + g + 8][kc];
            unsigned pa2 = Ps[w16 + g    ][kc + 4];
            unsigned pa3 = Ps[w16 + g + 8][kc + 4];
#pragma unroll
            for (int nf = 0; nf < 4; nf++) {
                int nc = (nf << 3) + g;
                mma8(o[nf], pa0, pa1, pa2, pa3,
                     Vs[cur][kc][nc], Vs[cur][kc + 4][nc]);
            }
        }
    }

    // ---- finalize: y += O / l ----
    float inv0 = 1.f / l0r;
    float inv1 = 1.f / l1r;
    int r0 = b * SEQ + qb0 + w16 + g;
    int r1 = r0 + 8;
#pragma unroll
    for (int nf = 0; nf < 4; nf++) {
        int col = h * HD + (nf << 3) + (i << 1);
        size_t i00 = (size_t)r0 * DIMC + col;
        size_t i10 = (size_t)r1 * DIMC + col;
        y[i00]     += o[nf][0] * inv0;
        y[i00 + 1] += o[nf][1] * inv0;
        y[i10]     += o[nf][2] * inv1;
        y[i10 + 1] += o[nf][3] * inv1;
    }
}

// ============================================================================
// launch
// ============================================================================
extern "C" void kernel_launch(void* const* d_in, const int* in_sizes, int n_in,
                              void* d_out, int out_size)
{
    const float* x      = (const float*)d_in[0];
    const float* w_qkv  = (const float*)d_in[1];
    const float* w_proj = (const float*)d_in[2];
    const float* b_proj = (const float*)d_in[3];
    const float* w_lepe = (const float*)d_in[4];
    const float* b_lepe = (const float*)d_in[5];
    float* out = (float*)d_out;

    void *p_qkv, *p_y, *p_xr, *p_yr, *p_wqr, *p_wpr;
    cudaGetSymbolAddress(&p_qkv, g_qkv);
    cudaGetSymbolAddress(&p_y,   g_y);
    cudaGetSymbolAddress(&p_xr,  g_xr);
    cudaGetSymbolAddress(&p_yr,  g_yr);
    cudaGetSymbolAddress(&p_wqr, g_wqr);
    cudaGetSymbolAddress(&p_wpr, g_wpr);
    float* qkv = (float*)p_qkv;
    float* y   = (float*)p_y;
    float* xr  = (float*)p_xr;
    float* yr  = (float*)p_yr;
    float* wqr = (float*)p_wqr;
    float* wpr = (float*)p_wpr;

    cudaFuncSetAttribute(gemm_tc, cudaFuncAttributeMaxDynamicSharedMemorySize,
                         G_SMEM);

    // 0) round inputs to tf32 (rna) once
    {
        int n4x = MTOT * DIMC / 4;          // 1048576
        int n4q = 3 * DIMC * DIMC / 4;      // 196608
        int n4p = DIMC * DIMC / 4;          // 65536
        round_tf32_k<<<(n4x + 255) / 256, 256>>>(x,      xr,  n4x);
        round_tf32_k<<<(n4q + 255) / 256, 256>>>(w_qkv,  wqr, n4q);
        round_tf32_k<<<(n4p + 255) / 256, 256>>>(w_proj, wpr, n4p);
    }

    // 1) QKV GEMM (tf32-exact output for attention)
    gemm_tc<<<dim3(3 * DIMC / 128, MTOT / 128), 256, G_SMEM>>>(
        xr, wqr, qkv, MTOT, 3 * DIMC, DIMC, nullptr, 1);
    // 2) LePE conv -> y (exact fp32)
    lepe_conv<<<dim3(8, 32, BATCH), 256>>>(x, w_lepe, b_lepe, y);
    // 3) attention, y += attn_out
    attn_tc<<<dim3(SEQ / QB, HEADS, BATCH), 256>>>(qkv, y);
    // 4) round y for proj
    {
        int n4y = MTOT * DIMC / 4;
        round_tf32_k<<<(n4y + 255) / 256, 256>>>(y, yr, n4y);
    }
    // 5) proj: out = yr @ wpr^T + b_proj
    gemm_tc<<<dim3(DIMC / 128, MTOT / 128), 256, G_SMEM>>>(
        yr, wpr, out, MTOT, DIMC, DIMC, b_proj, 0);
}